// round 9
// baseline (speedup 1.0000x reference)
#include <cuda_runtime.h>
#include <cstdint>

// QuantumCircuitSimulator2: 24 qubits, 8 steps of 4-qubit (16x16 complex) gates.
// Round-2 architecture (one gate per kernel, per-thread 16-amplitude group,
// global gather/scatter) improved:
//   - state held as interleaved float2 in a __device__ scratch between steps
//     (first kernel converts planar->interleaved, last converts back)
//   - 4-mult complex matvec on fma.rn.f32x2 (2 tables, 4 chains)
//   - 3 blocks/SM via reduced register footprint

#define NQ 24
#define NSTATE (1u << NQ)
#define NGROUPS (1u << (NQ - 4))
#define NSTEPS 8

typedef unsigned long long u64;

// interleaved scratch state (float2 per amplitude) — static device array
__device__ __align__(16) float QS_scratch[1u << 25];

__device__ __forceinline__ u64 fma2(u64 a, u64 b, u64 c) {
    u64 d;
    asm("fma.rn.f32x2 %0, %1, %2, %3;" : "=l"(d) : "l"(a), "l"(b), "l"(c));
    return d;
}
__device__ __forceinline__ u64 add2(u64 a, u64 b) {
    u64 d;
    asm("add.rn.f32x2 %0, %1, %2;" : "=l"(d) : "l"(a), "l"(b));
    return d;
}
__device__ __forceinline__ u64 pack2(float lo, float hi) {
    u64 d;
    asm("mov.b64 %0, {%1, %2};" : "=l"(d) : "f"(lo), "f"(hi));
    return d;
}
__device__ __forceinline__ void unpack2(u64 v, float& lo, float& hi) {
    asm("mov.b64 {%0, %1}, %2;" : "=f"(lo), "=f"(hi) : "l"(v));
}

// IN_PLANAR: src is [2, 2^24] planar re/im. Otherwise interleaved float2.
// OUT_PLANAR: dst is planar. Otherwise interleaved float2.
template <int IN_PLANAR, int OUT_PLANAR>
__global__ __launch_bounds__(256, 3)
void qgate_kernel(const float* __restrict__ src,
                  float* __restrict__ dst,
                  const float* __restrict__ gates,
                  const int* __restrict__ targets_raw,
                  int step) {
    __shared__ __align__(16) float sGr[256];
    __shared__ __align__(16) float sGi[256];

    const int tid = threadIdx.x;

    // raw gate tables (gr, gi) for this step
    {
        const float* g = gates + (size_t)step * 512;
        sGr[tid] = g[tid];
        sGi[tid] = g[256 + tid];
    }

    // dtype detect: int64 targets (<24) have zero odd 32-bit words
    int stride = (targets_raw[1] == 0 && targets_raw[3] == 0) ? 2 : 1;
    int q0 = targets_raw[(step * 4 + 0) * stride];
    int q1 = targets_raw[(step * 4 + 1) * stride];
    int q2 = targets_raw[(step * 4 + 2) * stride];
    int q3 = targets_raw[(step * 4 + 3) * stride];
    unsigned m0 = 1u << q0, m1 = 1u << q1, m2 = 1u << q2, m3 = 1u << q3;

    // sorted copy for ascending zero-bit insertion
    int a = q0, b = q1, c = q2, d = q3, t;
    if (a > b) { t = a; a = b; b = t; }
    if (c > d) { t = c; c = d; d = t; }
    if (a > c) { t = a; a = c; c = t; }
    if (b > d) { t = b; b = d; d = t; }
    if (b > c) { t = b; b = c; c = t; }

    unsigned g20 = blockIdx.x * 256u + tid;
    unsigned base = g20;
    base = ((base >> a) << (a + 1)) | (base & ((1u << a) - 1u));
    base = ((base >> b) << (b + 1)) | (base & ((1u << b) - 1u));
    base = ((base >> c) << (c + 1)) | (base & ((1u << c) - 1u));
    base = ((base >> d) << (d + 1)) | (base & ((1u << d) - 1u));

    // ---- gather 16 amplitudes, pack along k into f32x2 pairs ----
    u64 sr2[8], si2[8];
#pragma unroll
    for (int kk = 0; kk < 8; kk++) {
        unsigned o0 = base + (((2 * kk) & 1) ? m0 : 0u) + ((kk & 1) ? m1 : 0u) +
                      ((kk & 2) ? m2 : 0u) + ((kk & 4) ? m3 : 0u);
        unsigned o1 = o0 + m0;
        float r0, i0, r1, i1;
        if (IN_PLANAR) {
            r0 = src[o0];
            i0 = src[NSTATE + o0];
            r1 = src[o1];
            i1 = src[NSTATE + o1];
        } else {
            const float2* s2 = reinterpret_cast<const float2*>(src);
            float2 v0 = s2[o0];
            float2 v1 = s2[o1];
            r0 = v0.x; i0 = v0.y;
            r1 = v1.x; i1 = v1.y;
        }
        sr2[kk] = pack2(r0, r1);
        si2[kk] = pack2(i0, i1);
    }

    __syncthreads();  // tables ready (gathers overlap the table fill)

    const u64 NEG1 = pack2(-1.0f, -1.0f);
#pragma unroll
    for (int j = 0; j < 16; j++) {
        const float4* Gr4 = reinterpret_cast<const float4*>(sGr + j * 16);
        const float4* Gi4 = reinterpret_cast<const float4*>(sGi + j * 16);
        u64 a1 = 0ull, a2 = 0ull, a3 = 0ull, a4 = 0ull;
#pragma unroll
        for (int q = 0; q < 4; q++) {
            float4 gr = Gr4[q];
            float4 gi = Gi4[q];
            u64 grLo = pack2(gr.x, gr.y), grHi = pack2(gr.z, gr.w);
            u64 giLo = pack2(gi.x, gi.y), giHi = pack2(gi.z, gi.w);
            a1 = fma2(grLo, sr2[2 * q], a1);      // gr*sr
            a2 = fma2(giLo, si2[2 * q], a2);      // gi*si
            a3 = fma2(grLo, si2[2 * q], a3);      // gr*si
            a4 = fma2(giLo, sr2[2 * q], a4);      // gi*sr
            a1 = fma2(grHi, sr2[2 * q + 1], a1);
            a2 = fma2(giHi, si2[2 * q + 1], a2);
            a3 = fma2(grHi, si2[2 * q + 1], a3);
            a4 = fma2(giHi, sr2[2 * q + 1], a4);
        }
        u64 dre = fma2(a2, NEG1, a1);   // a1 - a2
        u64 dim = add2(a3, a4);         // a3 + a4
        float rl, rh, il, ih;
        unpack2(dre, rl, rh);
        unpack2(dim, il, ih);
        float re = rl + rh;
        float im = il + ih;
        unsigned oj = base + ((j & 1) ? m0 : 0u) + ((j & 2) ? m1 : 0u) +
                      ((j & 4) ? m2 : 0u) + ((j & 8) ? m3 : 0u);
        if (OUT_PLANAR) {
            dst[oj] = re;
            dst[NSTATE + oj] = im;
        } else {
            reinterpret_cast<float2*>(dst)[oj] = make_float2(re, im);
        }
    }
}

extern "C" void kernel_launch(void* const* d_in, const int* in_sizes, int n_in,
                              void* d_out, int out_size) {
    const float* state   = (const float*)d_in[0];
    const int*   targets = (const int*)d_in[1];
    const float* gates   = (const float*)d_in[2];
    float*       out     = (float*)d_out;

    void* scratch_ptr = nullptr;
    cudaGetSymbolAddress(&scratch_ptr, QS_scratch);
    float* scratch = (float*)scratch_ptr;

    dim3 block(256);
    dim3 grid(NGROUPS / 256);  // 4096 blocks

    // step 0: planar input -> interleaved scratch
    qgate_kernel<1, 0><<<grid, block>>>(state, scratch, gates, targets, 0);
    // steps 1..6: interleaved in-place (each thread owns its group)
    for (int s = 1; s < NSTEPS - 1; s++) {
        qgate_kernel<0, 0><<<grid, block>>>(scratch, scratch, gates, targets, s);
    }
    // step 7: interleaved -> planar output
    qgate_kernel<0, 1><<<grid, block>>>(scratch, out, gates, targets, NSTEPS - 1);
}

// round 10
// speedup vs baseline: 1.6296x; 1.6296x over previous
#include <cuda_runtime.h>
#include <cstdint>

// QuantumCircuitSimulator2: 24 qubits, 8 steps of 4-qubit (16x16 complex) gates.
// Round-2 architecture (one gate per kernel, per-thread 16-amplitude group,
// global gather/scatter) improved:
//   - state held as interleaved float2 in a __device__ scratch between steps
//     (first kernel converts planar->interleaved, last converts back)
//   - 4-mult complex matvec on fma.rn.f32x2 (2 tables, 4 chains)
//   - 3 blocks/SM via reduced register footprint

#define NQ 24
#define NSTATE (1u << NQ)
#define NGROUPS (1u << (NQ - 4))
#define NSTEPS 8

typedef unsigned long long u64;

// interleaved scratch state (float2 per amplitude) — static device array
__device__ __align__(16) float QS_scratch[1u << 25];

__device__ __forceinline__ u64 fma2(u64 a, u64 b, u64 c) {
    u64 d;
    asm("fma.rn.f32x2 %0, %1, %2, %3;" : "=l"(d) : "l"(a), "l"(b), "l"(c));
    return d;
}
__device__ __forceinline__ u64 add2(u64 a, u64 b) {
    u64 d;
    asm("add.rn.f32x2 %0, %1, %2;" : "=l"(d) : "l"(a), "l"(b));
    return d;
}
__device__ __forceinline__ u64 pack2(float lo, float hi) {
    u64 d;
    asm("mov.b64 %0, {%1, %2};" : "=l"(d) : "f"(lo), "f"(hi));
    return d;
}
__device__ __forceinline__ void unpack2(u64 v, float& lo, float& hi) {
    asm("mov.b64 {%0, %1}, %2;" : "=f"(lo), "=f"(hi) : "l"(v));
}

// IN_PLANAR: src is [2, 2^24] planar re/im. Otherwise interleaved float2.
// OUT_PLANAR: dst is planar. Otherwise interleaved float2.
template <int IN_PLANAR, int OUT_PLANAR>
__global__ __launch_bounds__(256, 3)
void qgate_kernel(const float* __restrict__ src,
                  float* __restrict__ dst,
                  const float* __restrict__ gates,
                  const int* __restrict__ targets_raw,
                  int step) {
    __shared__ __align__(16) float sGr[256];
    __shared__ __align__(16) float sGi[256];

    const int tid = threadIdx.x;

    // raw gate tables (gr, gi) for this step
    {
        const float* g = gates + (size_t)step * 512;
        sGr[tid] = g[tid];
        sGi[tid] = g[256 + tid];
    }

    // dtype detect: int64 targets (<24) have zero odd 32-bit words
    int stride = (targets_raw[1] == 0 && targets_raw[3] == 0) ? 2 : 1;
    int q0 = targets_raw[(step * 4 + 0) * stride];
    int q1 = targets_raw[(step * 4 + 1) * stride];
    int q2 = targets_raw[(step * 4 + 2) * stride];
    int q3 = targets_raw[(step * 4 + 3) * stride];
    unsigned m0 = 1u << q0, m1 = 1u << q1, m2 = 1u << q2, m3 = 1u << q3;

    // sorted copy for ascending zero-bit insertion
    int a = q0, b = q1, c = q2, d = q3, t;
    if (a > b) { t = a; a = b; b = t; }
    if (c > d) { t = c; c = d; d = t; }
    if (a > c) { t = a; a = c; c = t; }
    if (b > d) { t = b; b = d; d = t; }
    if (b > c) { t = b; b = c; c = t; }

    unsigned g20 = blockIdx.x * 256u + tid;
    unsigned base = g20;
    base = ((base >> a) << (a + 1)) | (base & ((1u << a) - 1u));
    base = ((base >> b) << (b + 1)) | (base & ((1u << b) - 1u));
    base = ((base >> c) << (c + 1)) | (base & ((1u << c) - 1u));
    base = ((base >> d) << (d + 1)) | (base & ((1u << d) - 1u));

    // ---- gather 16 amplitudes, pack along k into f32x2 pairs ----
    u64 sr2[8], si2[8];
#pragma unroll
    for (int kk = 0; kk < 8; kk++) {
        unsigned o0 = base + (((2 * kk) & 1) ? m0 : 0u) + ((kk & 1) ? m1 : 0u) +
                      ((kk & 2) ? m2 : 0u) + ((kk & 4) ? m3 : 0u);
        unsigned o1 = o0 + m0;
        float r0, i0, r1, i1;
        if (IN_PLANAR) {
            r0 = src[o0];
            i0 = src[NSTATE + o0];
            r1 = src[o1];
            i1 = src[NSTATE + o1];
        } else {
            const float2* s2 = reinterpret_cast<const float2*>(src);
            float2 v0 = s2[o0];
            float2 v1 = s2[o1];
            r0 = v0.x; i0 = v0.y;
            r1 = v1.x; i1 = v1.y;
        }
        sr2[kk] = pack2(r0, r1);
        si2[kk] = pack2(i0, i1);
    }

    __syncthreads();  // tables ready (gathers overlap the table fill)

    const u64 NEG1 = pack2(-1.0f, -1.0f);
#pragma unroll
    for (int j = 0; j < 16; j++) {
        const float4* Gr4 = reinterpret_cast<const float4*>(sGr + j * 16);
        const float4* Gi4 = reinterpret_cast<const float4*>(sGi + j * 16);
        u64 a1 = 0ull, a2 = 0ull, a3 = 0ull, a4 = 0ull;
#pragma unroll
        for (int q = 0; q < 4; q++) {
            float4 gr = Gr4[q];
            float4 gi = Gi4[q];
            u64 grLo = pack2(gr.x, gr.y), grHi = pack2(gr.z, gr.w);
            u64 giLo = pack2(gi.x, gi.y), giHi = pack2(gi.z, gi.w);
            a1 = fma2(grLo, sr2[2 * q], a1);      // gr*sr
            a2 = fma2(giLo, si2[2 * q], a2);      // gi*si
            a3 = fma2(grLo, si2[2 * q], a3);      // gr*si
            a4 = fma2(giLo, sr2[2 * q], a4);      // gi*sr
            a1 = fma2(grHi, sr2[2 * q + 1], a1);
            a2 = fma2(giHi, si2[2 * q + 1], a2);
            a3 = fma2(grHi, si2[2 * q + 1], a3);
            a4 = fma2(giHi, sr2[2 * q + 1], a4);
        }
        u64 dre = fma2(a2, NEG1, a1);   // a1 - a2
        u64 dim = add2(a3, a4);         // a3 + a4
        float rl, rh, il, ih;
        unpack2(dre, rl, rh);
        unpack2(dim, il, ih);
        float re = rl + rh;
        float im = il + ih;
        unsigned oj = base + ((j & 1) ? m0 : 0u) + ((j & 2) ? m1 : 0u) +
                      ((j & 4) ? m2 : 0u) + ((j & 8) ? m3 : 0u);
        if (OUT_PLANAR) {
            dst[oj] = re;
            dst[NSTATE + oj] = im;
        } else {
            reinterpret_cast<float2*>(dst)[oj] = make_float2(re, im);
        }
    }
}

extern "C" void kernel_launch(void* const* d_in, const int* in_sizes, int n_in,
                              void* d_out, int out_size) {
    const float* state   = (const float*)d_in[0];
    const int*   targets = (const int*)d_in[1];
    const float* gates   = (const float*)d_in[2];
    float*       out     = (float*)d_out;

    void* scratch_ptr = nullptr;
    cudaGetSymbolAddress(&scratch_ptr, QS_scratch);
    float* scratch = (float*)scratch_ptr;

    dim3 block(256);
    dim3 grid(NGROUPS / 256);  // 4096 blocks

    // step 0: planar input -> interleaved scratch
    qgate_kernel<1, 0><<<grid, block>>>(state, scratch, gates, targets, 0);
    // steps 1..6: interleaved in-place (each thread owns its group)
    for (int s = 1; s < NSTEPS - 1; s++) {
        qgate_kernel<0, 0><<<grid, block>>>(scratch, scratch, gates, targets, s);
    }
    // step 7: interleaved -> planar output
    qgate_kernel<0, 1><<<grid, block>>>(scratch, out, gates, targets, NSTEPS - 1);
}

// round 11
// speedup vs baseline: 1.6301x; 1.0003x over previous
#include <cuda_runtime.h>
#include <cstdint>

// QuantumCircuitSimulator2: 24 qubits, 8 steps of 4-qubit (16x16 complex) gates.
// One gate per kernel, per-thread 16-amplitude group, global gather/scatter.
//   - interleaved float2 state in __device__ scratch between steps
//   - 4-mult complex matvec on fma.rn.f32x2
//   - gate tables read as ulonglong2 (LDS.128) whose halves ARE the packed
//     f32x2 operands -> zero repacking movs (round-10 ALU bottleneck)

#define NQ 24
#define NSTATE (1u << NQ)
#define NGROUPS (1u << (NQ - 4))
#define NSTEPS 8

typedef unsigned long long u64;

// interleaved scratch state (float2 per amplitude) — static device array
__device__ __align__(16) float QS_scratch[1u << 25];

__device__ __forceinline__ u64 fma2(u64 a, u64 b, u64 c) {
    u64 d;
    asm("fma.rn.f32x2 %0, %1, %2, %3;" : "=l"(d) : "l"(a), "l"(b), "l"(c));
    return d;
}
__device__ __forceinline__ u64 add2(u64 a, u64 b) {
    u64 d;
    asm("add.rn.f32x2 %0, %1, %2;" : "=l"(d) : "l"(a), "l"(b));
    return d;
}
__device__ __forceinline__ u64 pack2(float lo, float hi) {
    u64 d;
    asm("mov.b64 %0, {%1, %2};" : "=l"(d) : "f"(lo), "f"(hi));
    return d;
}
__device__ __forceinline__ void unpack2(u64 v, float& lo, float& hi) {
    asm("mov.b64 {%0, %1}, %2;" : "=f"(lo), "=f"(hi) : "l"(v));
}

// IN_PLANAR: src is [2, 2^24] planar re/im. Otherwise interleaved float2.
// OUT_PLANAR: dst is planar. Otherwise interleaved float2.
template <int IN_PLANAR, int OUT_PLANAR>
__global__ __launch_bounds__(256, 3)
void qgate_kernel(const float* __restrict__ src,
                  float* __restrict__ dst,
                  const float* __restrict__ gates,
                  const int* __restrict__ targets_raw,
                  int step) {
    __shared__ __align__(16) float sGr[256];
    __shared__ __align__(16) float sGi[256];

    const int tid = threadIdx.x;

    // raw gate tables (gr, gi) for this step
    {
        const float* g = gates + (size_t)step * 512;
        sGr[tid] = g[tid];
        sGi[tid] = g[256 + tid];
    }

    // dtype detect: int64 targets (<24) have zero odd 32-bit words
    int stride = (targets_raw[1] == 0 && targets_raw[3] == 0) ? 2 : 1;
    int q0 = targets_raw[(step * 4 + 0) * stride];
    int q1 = targets_raw[(step * 4 + 1) * stride];
    int q2 = targets_raw[(step * 4 + 2) * stride];
    int q3 = targets_raw[(step * 4 + 3) * stride];
    unsigned m0 = 1u << q0, m1 = 1u << q1, m2 = 1u << q2, m3 = 1u << q3;

    // sorted copy for ascending zero-bit insertion
    int a = q0, b = q1, c = q2, d = q3, t;
    if (a > b) { t = a; a = b; b = t; }
    if (c > d) { t = c; c = d; d = t; }
    if (a > c) { t = a; a = c; c = t; }
    if (b > d) { t = b; b = d; d = t; }
    if (b > c) { t = b; b = c; c = t; }

    unsigned g20 = blockIdx.x * 256u + tid;
    unsigned base = g20;
    base = ((base >> a) << (a + 1)) | (base & ((1u << a) - 1u));
    base = ((base >> b) << (b + 1)) | (base & ((1u << b) - 1u));
    base = ((base >> c) << (c + 1)) | (base & ((1u << c) - 1u));
    base = ((base >> d) << (d + 1)) | (base & ((1u << d) - 1u));

    // ---- gather 16 amplitudes, pack along k into f32x2 pairs ----
    u64 sr2[8], si2[8];
#pragma unroll
    for (int kk = 0; kk < 8; kk++) {
        unsigned o0 = base + ((kk & 1) ? m1 : 0u) +
                      ((kk & 2) ? m2 : 0u) + ((kk & 4) ? m3 : 0u);
        unsigned o1 = o0 + m0;
        float r0, i0, r1, i1;
        if (IN_PLANAR) {
            r0 = src[o0];
            i0 = src[NSTATE + o0];
            r1 = src[o1];
            i1 = src[NSTATE + o1];
        } else {
            const float2* s2 = reinterpret_cast<const float2*>(src);
            float2 v0 = s2[o0];
            float2 v1 = s2[o1];
            r0 = v0.x; i0 = v0.y;
            r1 = v1.x; i1 = v1.y;
        }
        sr2[kk] = pack2(r0, r1);
        si2[kk] = pack2(i0, i1);
    }

    __syncthreads();  // tables ready (gathers overlap the table fill)

    const u64 NEG1 = pack2(-1.0f, -1.0f);
#pragma unroll
    for (int j = 0; j < 16; j++) {
        // Each table row = 16 floats = 4 ulonglong2; .x/.y ARE the packed
        // f32x2 operand pairs (zero-mov path).
        const ulonglong2* Gr2 = reinterpret_cast<const ulonglong2*>(sGr + j * 16);
        const ulonglong2* Gi2 = reinterpret_cast<const ulonglong2*>(sGi + j * 16);
        u64 a1 = 0ull, a2 = 0ull, a3 = 0ull, a4 = 0ull;
#pragma unroll
        for (int q = 0; q < 4; q++) {
            ulonglong2 gr = Gr2[q];
            ulonglong2 gi = Gi2[q];
            a1 = fma2(gr.x, sr2[2 * q], a1);      // gr*sr
            a2 = fma2(gi.x, si2[2 * q], a2);      // gi*si
            a3 = fma2(gr.x, si2[2 * q], a3);      // gr*si
            a4 = fma2(gi.x, sr2[2 * q], a4);      // gi*sr
            a1 = fma2(gr.y, sr2[2 * q + 1], a1);
            a2 = fma2(gi.y, si2[2 * q + 1], a2);
            a3 = fma2(gr.y, si2[2 * q + 1], a3);
            a4 = fma2(gi.y, sr2[2 * q + 1], a4);
        }
        u64 dre = fma2(a2, NEG1, a1);   // a1 - a2
        u64 dim = add2(a3, a4);         // a3 + a4
        float rl, rh, il, ih;
        unpack2(dre, rl, rh);
        unpack2(dim, il, ih);
        float re = rl + rh;
        float im = il + ih;
        unsigned oj = base + ((j & 1) ? m0 : 0u) + ((j & 2) ? m1 : 0u) +
                      ((j & 4) ? m2 : 0u) + ((j & 8) ? m3 : 0u);
        if (OUT_PLANAR) {
            dst[oj] = re;
            dst[NSTATE + oj] = im;
        } else {
            reinterpret_cast<float2*>(dst)[oj] = make_float2(re, im);
        }
    }
}

extern "C" void kernel_launch(void* const* d_in, const int* in_sizes, int n_in,
                              void* d_out, int out_size) {
    const float* state   = (const float*)d_in[0];
    const int*   targets = (const int*)d_in[1];
    const float* gates   = (const float*)d_in[2];
    float*       out     = (float*)d_out;

    void* scratch_ptr = nullptr;
    cudaGetSymbolAddress(&scratch_ptr, QS_scratch);
    float* scratch = (float*)scratch_ptr;

    dim3 block(256);
    dim3 grid(NGROUPS / 256);  // 4096 blocks

    // step 0: planar input -> interleaved scratch
    qgate_kernel<1, 0><<<grid, block>>>(state, scratch, gates, targets, 0);
    // steps 1..6: interleaved in-place (each thread owns its group)
    for (int s = 1; s < NSTEPS - 1; s++) {
        qgate_kernel<0, 0><<<grid, block>>>(scratch, scratch, gates, targets, s);
    }
    // step 7: interleaved -> planar output
    qgate_kernel<0, 1><<<grid, block>>>(scratch, out, gates, targets, NSTEPS - 1);
}

// round 12
// speedup vs baseline: 1.6308x; 1.0005x over previous
#include <cuda_runtime.h>
#include <cstdint>

// QuantumCircuitSimulator2: 24 qubits, 8 steps of 4-qubit (16x16 complex) gates.
// One gate per kernel, per-thread 16-amplitude group, global gather/scatter.
//   - interleaved float2 state in __device__ scratch between steps
//   - 4-mult complex matvec on fma.rn.f32x2
//   - accumulators via "+l" read-write asm constraint (in-place FFMA2, no
//     mov-copy per fma), first term via mul.rn.f32x2 (no zero-init movs)

#define NQ 24
#define NSTATE (1u << NQ)
#define NGROUPS (1u << (NQ - 4))
#define NSTEPS 8

typedef unsigned long long u64;

// interleaved scratch state (float2 per amplitude) — static device array
__device__ __align__(16) float QS_scratch[1u << 25];

__device__ __forceinline__ void fma2_acc(u64& acc, u64 a, u64 b) {
    asm("fma.rn.f32x2 %0, %1, %2, %0;" : "+l"(acc) : "l"(a), "l"(b));
}
__device__ __forceinline__ u64 mul2(u64 a, u64 b) {
    u64 d;
    asm("mul.rn.f32x2 %0, %1, %2;" : "=l"(d) : "l"(a), "l"(b));
    return d;
}
__device__ __forceinline__ u64 fma2(u64 a, u64 b, u64 c) {
    u64 d;
    asm("fma.rn.f32x2 %0, %1, %2, %3;" : "=l"(d) : "l"(a), "l"(b), "l"(c));
    return d;
}
__device__ __forceinline__ u64 add2(u64 a, u64 b) {
    u64 d;
    asm("add.rn.f32x2 %0, %1, %2;" : "=l"(d) : "l"(a), "l"(b));
    return d;
}
__device__ __forceinline__ u64 pack2(float lo, float hi) {
    u64 d;
    asm("mov.b64 %0, {%1, %2};" : "=l"(d) : "f"(lo), "f"(hi));
    return d;
}
__device__ __forceinline__ void unpack2(u64 v, float& lo, float& hi) {
    asm("mov.b64 {%0, %1}, %2;" : "=f"(lo), "=f"(hi) : "l"(v));
}

// IN_PLANAR: src is [2, 2^24] planar re/im. Otherwise interleaved float2.
// OUT_PLANAR: dst is planar. Otherwise interleaved float2.
template <int IN_PLANAR, int OUT_PLANAR>
__global__ __launch_bounds__(256, 3)
void qgate_kernel(const float* __restrict__ src,
                  float* __restrict__ dst,
                  const float* __restrict__ gates,
                  const int* __restrict__ targets_raw,
                  int step) {
    __shared__ __align__(16) float sGr[256];
    __shared__ __align__(16) float sGi[256];

    const int tid = threadIdx.x;

    // raw gate tables (gr, gi) for this step
    {
        const float* g = gates + (size_t)step * 512;
        sGr[tid] = g[tid];
        sGi[tid] = g[256 + tid];
    }

    // dtype detect: int64 targets (<24) have zero odd 32-bit words
    int stride = (targets_raw[1] == 0 && targets_raw[3] == 0) ? 2 : 1;
    int q0 = targets_raw[(step * 4 + 0) * stride];
    int q1 = targets_raw[(step * 4 + 1) * stride];
    int q2 = targets_raw[(step * 4 + 2) * stride];
    int q3 = targets_raw[(step * 4 + 3) * stride];
    unsigned m0 = 1u << q0, m1 = 1u << q1, m2 = 1u << q2, m3 = 1u << q3;

    // sorted copy for ascending zero-bit insertion
    int a = q0, b = q1, c = q2, d = q3, t;
    if (a > b) { t = a; a = b; b = t; }
    if (c > d) { t = c; c = d; d = t; }
    if (a > c) { t = a; a = c; c = t; }
    if (b > d) { t = b; b = d; d = t; }
    if (b > c) { t = b; b = c; c = t; }

    unsigned g20 = blockIdx.x * 256u + tid;
    unsigned base = g20;
    base = ((base >> a) << (a + 1)) | (base & ((1u << a) - 1u));
    base = ((base >> b) << (b + 1)) | (base & ((1u << b) - 1u));
    base = ((base >> c) << (c + 1)) | (base & ((1u << c) - 1u));
    base = ((base >> d) << (d + 1)) | (base & ((1u << d) - 1u));

    // ---- gather 16 amplitudes, pack along k into f32x2 pairs ----
    u64 sr2[8], si2[8];
#pragma unroll
    for (int kk = 0; kk < 8; kk++) {
        unsigned o0 = base + ((kk & 1) ? m1 : 0u) +
                      ((kk & 2) ? m2 : 0u) + ((kk & 4) ? m3 : 0u);
        unsigned o1 = o0 + m0;
        float r0, i0, r1, i1;
        if (IN_PLANAR) {
            r0 = src[o0];
            i0 = src[NSTATE + o0];
            r1 = src[o1];
            i1 = src[NSTATE + o1];
        } else {
            const float2* s2 = reinterpret_cast<const float2*>(src);
            float2 v0 = s2[o0];
            float2 v1 = s2[o1];
            r0 = v0.x; i0 = v0.y;
            r1 = v1.x; i1 = v1.y;
        }
        sr2[kk] = pack2(r0, r1);
        si2[kk] = pack2(i0, i1);
    }

    __syncthreads();  // tables ready (gathers overlap the table fill)

    const u64 NEG1 = pack2(-1.0f, -1.0f);
#pragma unroll
    for (int j = 0; j < 16; j++) {
        // Each table row = 16 floats = 4 ulonglong2; .x/.y ARE the packed
        // f32x2 operand pairs.
        const ulonglong2* Gr2 = reinterpret_cast<const ulonglong2*>(sGr + j * 16);
        const ulonglong2* Gi2 = reinterpret_cast<const ulonglong2*>(sGi + j * 16);
        ulonglong2 gr0 = Gr2[0];
        ulonglong2 gi0 = Gi2[0];
        u64 a1 = mul2(gr0.x, sr2[0]);   // gr*sr
        u64 a2 = mul2(gi0.x, si2[0]);   // gi*si
        u64 a3 = mul2(gr0.x, si2[0]);   // gr*si
        u64 a4 = mul2(gi0.x, sr2[0]);   // gi*sr
        fma2_acc(a1, gr0.y, sr2[1]);
        fma2_acc(a2, gi0.y, si2[1]);
        fma2_acc(a3, gr0.y, si2[1]);
        fma2_acc(a4, gi0.y, sr2[1]);
#pragma unroll
        for (int q = 1; q < 4; q++) {
            ulonglong2 gr = Gr2[q];
            ulonglong2 gi = Gi2[q];
            fma2_acc(a1, gr.x, sr2[2 * q]);
            fma2_acc(a2, gi.x, si2[2 * q]);
            fma2_acc(a3, gr.x, si2[2 * q]);
            fma2_acc(a4, gi.x, sr2[2 * q]);
            fma2_acc(a1, gr.y, sr2[2 * q + 1]);
            fma2_acc(a2, gi.y, si2[2 * q + 1]);
            fma2_acc(a3, gr.y, si2[2 * q + 1]);
            fma2_acc(a4, gi.y, sr2[2 * q + 1]);
        }
        fma2_acc(a1, a2, NEG1);         // a1 = a1 - a2  (acc += a2 * -1)
        u64 dim = add2(a3, a4);         // a3 + a4
        float rl, rh, il, ih;
        unpack2(a1, rl, rh);
        unpack2(dim, il, ih);
        float re = rl + rh;
        float im = il + ih;
        unsigned oj = base + ((j & 1) ? m0 : 0u) + ((j & 2) ? m1 : 0u) +
                      ((j & 4) ? m2 : 0u) + ((j & 8) ? m3 : 0u);
        if (OUT_PLANAR) {
            dst[oj] = re;
            dst[NSTATE + oj] = im;
        } else {
            reinterpret_cast<float2*>(dst)[oj] = make_float2(re, im);
        }
    }
}

extern "C" void kernel_launch(void* const* d_in, const int* in_sizes, int n_in,
                              void* d_out, int out_size) {
    const float* state   = (const float*)d_in[0];
    const int*   targets = (const int*)d_in[1];
    const float* gates   = (const float*)d_in[2];
    float*       out     = (float*)d_out;

    void* scratch_ptr = nullptr;
    cudaGetSymbolAddress(&scratch_ptr, QS_scratch);
    float* scratch = (float*)scratch_ptr;

    dim3 block(256);
    dim3 grid(NGROUPS / 256);  // 4096 blocks

    // step 0: planar input -> interleaved scratch
    qgate_kernel<1, 0><<<grid, block>>>(state, scratch, gates, targets, 0);
    // steps 1..6: interleaved in-place (each thread owns its group)
    for (int s = 1; s < NSTEPS - 1; s++) {
        qgate_kernel<0, 0><<<grid, block>>>(scratch, scratch, gates, targets, s);
    }
    // step 7: interleaved -> planar output
    qgate_kernel<0, 1><<<grid, block>>>(scratch, out, gates, targets, NSTEPS - 1);
}

// round 13
// speedup vs baseline: 1.9801x; 1.2141x over previous
#include <cuda_runtime.h>
#include <cstdint>

// QuantumCircuitSimulator2: 24 qubits, 8 steps of 4-qubit (16x16 complex) gates.
// One gate per kernel, per-thread 16-amplitude group, global gather/scatter.
//   - interleaved float2 state in __device__ scratch between steps
//   - 4-mult complex matvec on fma.rn.f32x2
//   - gate tables in __constant__ memory (uploaded once via
//     cudaMemcpyToSymbolAsync): uniform LDCU path, zero L1/SMEM traffic,
//     no __syncthreads

#define NQ 24
#define NSTATE (1u << NQ)
#define NGROUPS (1u << (NQ - 4))
#define NSTEPS 8

typedef unsigned long long u64;

// interleaved scratch state (float2 per amplitude) — static device array
__device__ __align__(16) float QS_scratch[1u << 25];

// all 8 gates: [step][2(re/im)][16][16] floats = 16 KB
__constant__ __align__(16) float cG[NSTEPS * 512];

__device__ __forceinline__ void fma2_acc(u64& acc, u64 a, u64 b) {
    asm("fma.rn.f32x2 %0, %1, %2, %0;" : "+l"(acc) : "l"(a), "l"(b));
}
__device__ __forceinline__ u64 mul2(u64 a, u64 b) {
    u64 d;
    asm("mul.rn.f32x2 %0, %1, %2;" : "=l"(d) : "l"(a), "l"(b));
    return d;
}
__device__ __forceinline__ u64 add2(u64 a, u64 b) {
    u64 d;
    asm("add.rn.f32x2 %0, %1, %2;" : "=l"(d) : "l"(a), "l"(b));
    return d;
}
__device__ __forceinline__ u64 pack2(float lo, float hi) {
    u64 d;
    asm("mov.b64 %0, {%1, %2};" : "=l"(d) : "f"(lo), "f"(hi));
    return d;
}
__device__ __forceinline__ void unpack2(u64 v, float& lo, float& hi) {
    asm("mov.b64 {%0, %1}, %2;" : "=f"(lo), "=f"(hi) : "l"(v));
}

// IN_PLANAR: src is [2, 2^24] planar re/im. Otherwise interleaved float2.
// OUT_PLANAR: dst is planar. Otherwise interleaved float2.
template <int IN_PLANAR, int OUT_PLANAR>
__global__ __launch_bounds__(256, 3)
void qgate_kernel(const float* __restrict__ src,
                  float* __restrict__ dst,
                  const int* __restrict__ targets_raw,
                  int step) {
    const int tid = threadIdx.x;

    // dtype detect: int64 targets (<24) have zero odd 32-bit words
    int stride = (targets_raw[1] == 0 && targets_raw[3] == 0) ? 2 : 1;
    int q0 = targets_raw[(step * 4 + 0) * stride];
    int q1 = targets_raw[(step * 4 + 1) * stride];
    int q2 = targets_raw[(step * 4 + 2) * stride];
    int q3 = targets_raw[(step * 4 + 3) * stride];
    unsigned m0 = 1u << q0, m1 = 1u << q1, m2 = 1u << q2, m3 = 1u << q3;

    // sorted copy for ascending zero-bit insertion
    int a = q0, b = q1, c = q2, d = q3, t;
    if (a > b) { t = a; a = b; b = t; }
    if (c > d) { t = c; c = d; d = t; }
    if (a > c) { t = a; a = c; c = t; }
    if (b > d) { t = b; b = d; d = t; }
    if (b > c) { t = b; b = c; c = t; }

    unsigned g20 = blockIdx.x * 256u + tid;
    unsigned base = g20;
    base = ((base >> a) << (a + 1)) | (base & ((1u << a) - 1u));
    base = ((base >> b) << (b + 1)) | (base & ((1u << b) - 1u));
    base = ((base >> c) << (c + 1)) | (base & ((1u << c) - 1u));
    base = ((base >> d) << (d + 1)) | (base & ((1u << d) - 1u));

    // ---- gather 16 amplitudes, pack along k into f32x2 pairs ----
    u64 sr2[8], si2[8];
#pragma unroll
    for (int kk = 0; kk < 8; kk++) {
        unsigned o0 = base + ((kk & 1) ? m1 : 0u) +
                      ((kk & 2) ? m2 : 0u) + ((kk & 4) ? m3 : 0u);
        unsigned o1 = o0 + m0;
        float r0, i0, r1, i1;
        if (IN_PLANAR) {
            r0 = src[o0];
            i0 = src[NSTATE + o0];
            r1 = src[o1];
            i1 = src[NSTATE + o1];
        } else {
            const float2* s2 = reinterpret_cast<const float2*>(src);
            float2 v0 = s2[o0];
            float2 v1 = s2[o1];
            r0 = v0.x; i0 = v0.y;
            r1 = v1.x; i1 = v1.y;
        }
        sr2[kk] = pack2(r0, r1);
        si2[kk] = pack2(i0, i1);
    }

    const float* gbase = cG + step * 512;
    const u64 NEG1 = pack2(-1.0f, -1.0f);
#pragma unroll
    for (int j = 0; j < 16; j++) {
        // Table rows from __constant__: warp-uniform addresses -> LDCU path
        // (.x/.y of each ulonglong2 ARE the packed f32x2 operand pairs).
        const ulonglong2* Gr2 = reinterpret_cast<const ulonglong2*>(gbase + j * 16);
        const ulonglong2* Gi2 = reinterpret_cast<const ulonglong2*>(gbase + 256 + j * 16);
        ulonglong2 gr0 = Gr2[0];
        ulonglong2 gi0 = Gi2[0];
        u64 a1 = mul2(gr0.x, sr2[0]);   // gr*sr
        u64 a2 = mul2(gi0.x, si2[0]);   // gi*si
        u64 a3 = mul2(gr0.x, si2[0]);   // gr*si
        u64 a4 = mul2(gi0.x, sr2[0]);   // gi*sr
        fma2_acc(a1, gr0.y, sr2[1]);
        fma2_acc(a2, gi0.y, si2[1]);
        fma2_acc(a3, gr0.y, si2[1]);
        fma2_acc(a4, gi0.y, sr2[1]);
#pragma unroll
        for (int q = 1; q < 4; q++) {
            ulonglong2 gr = Gr2[q];
            ulonglong2 gi = Gi2[q];
            fma2_acc(a1, gr.x, sr2[2 * q]);
            fma2_acc(a2, gi.x, si2[2 * q]);
            fma2_acc(a3, gr.x, si2[2 * q]);
            fma2_acc(a4, gi.x, sr2[2 * q]);
            fma2_acc(a1, gr.y, sr2[2 * q + 1]);
            fma2_acc(a2, gi.y, si2[2 * q + 1]);
            fma2_acc(a3, gr.y, si2[2 * q + 1]);
            fma2_acc(a4, gi.y, sr2[2 * q + 1]);
        }
        fma2_acc(a1, a2, NEG1);         // a1 = a1 - a2
        u64 dim = add2(a3, a4);         // a3 + a4
        float rl, rh, il, ih;
        unpack2(a1, rl, rh);
        unpack2(dim, il, ih);
        float re = rl + rh;
        float im = il + ih;
        unsigned oj = base + ((j & 1) ? m0 : 0u) + ((j & 2) ? m1 : 0u) +
                      ((j & 4) ? m2 : 0u) + ((j & 8) ? m3 : 0u);
        if (OUT_PLANAR) {
            dst[oj] = re;
            dst[NSTATE + oj] = im;
        } else {
            reinterpret_cast<float2*>(dst)[oj] = make_float2(re, im);
        }
    }
}

extern "C" void kernel_launch(void* const* d_in, const int* in_sizes, int n_in,
                              void* d_out, int out_size) {
    const float* state   = (const float*)d_in[0];
    const int*   targets = (const int*)d_in[1];
    const float* gates   = (const float*)d_in[2];
    float*       out     = (float*)d_out;

    void* scratch_ptr = nullptr;
    cudaGetSymbolAddress(&scratch_ptr, QS_scratch);
    float* scratch = (float*)scratch_ptr;

    // upload all 8 gate matrices (16 KB) to constant memory — DtoD async,
    // graph-capturable
    cudaMemcpyToSymbolAsync(cG, gates, NSTEPS * 512 * sizeof(float), 0,
                            cudaMemcpyDeviceToDevice);

    dim3 block(256);
    dim3 grid(NGROUPS / 256);  // 4096 blocks

    // step 0: planar input -> interleaved scratch
    qgate_kernel<1, 0><<<grid, block>>>(state, scratch, targets, 0);
    // steps 1..6: interleaved in-place (each thread owns its group)
    for (int s = 1; s < NSTEPS - 1; s++) {
        qgate_kernel<0, 0><<<grid, block>>>(scratch, scratch, targets, s);
    }
    // step 7: interleaved -> planar output
    qgate_kernel<0, 1><<<grid, block>>>(scratch, out, targets, NSTEPS - 1);
}

// round 14
// speedup vs baseline: 2.2172x; 1.1198x over previous
#include <cuda_runtime.h>
#include <cstdint>

// QuantumCircuitSimulator2: 24 qubits, 8 steps of 4-qubit (16x16 complex) gates.
// One gate per kernel, per-thread 16-amplitude group, global gather/scatter.
//   - interleaved float2 state in __device__ scratch between steps
//   - KARATSUBA complex matvec (3 chains) on fma.rn.f32x2: tables A=gr,
//     B=gr+gi, C=gi-gr precomputed by a prep kernel, served from __constant__
//     memory (uniform LDCU port -> extra table stream is ~free)

#define NQ 24
#define NSTATE (1u << NQ)
#define NGROUPS (1u << (NQ - 4))
#define NSTEPS 8

typedef unsigned long long u64;

// interleaved scratch state (float2 per amplitude) — static device array
__device__ __align__(16) float QS_scratch[1u << 25];
// staging for Karatsuba tables before upload to constant
__device__ __align__(16) float QS_tables[NSTEPS * 768];

// Karatsuba tables: [step][3][16][16] floats = 24 KB
__constant__ __align__(16) float cGK[NSTEPS * 768];

__device__ __forceinline__ void fma2_acc(u64& acc, u64 a, u64 b) {
    asm("fma.rn.f32x2 %0, %1, %2, %0;" : "+l"(acc) : "l"(a), "l"(b));
}
__device__ __forceinline__ u64 mul2(u64 a, u64 b) {
    u64 d;
    asm("mul.rn.f32x2 %0, %1, %2;" : "=l"(d) : "l"(a), "l"(b));
    return d;
}
__device__ __forceinline__ u64 add2(u64 a, u64 b) {
    u64 d;
    asm("add.rn.f32x2 %0, %1, %2;" : "=l"(d) : "l"(a), "l"(b));
    return d;
}
__device__ __forceinline__ u64 pack2(float lo, float hi) {
    u64 d;
    asm("mov.b64 %0, {%1, %2};" : "=l"(d) : "f"(lo), "f"(hi));
    return d;
}
__device__ __forceinline__ void unpack2(u64 v, float& lo, float& hi) {
    asm("mov.b64 {%0, %1}, %2;" : "=f"(lo), "=f"(hi) : "l"(v));
}

// Build Karatsuba tables for all steps: A=gr, B=gr+gi, C=gi-gr.
__global__ void qprep_kernel(const float* __restrict__ gates) {
    int step = blockIdx.x;
    const float* g = gates + (size_t)step * 512;
    for (int i = threadIdx.x; i < 768; i += blockDim.x) {
        int t = i >> 8;
        int idx = i & 255;
        float gr = g[idx];
        float gi = g[256 + idx];
        QS_tables[step * 768 + i] =
            (t == 0) ? gr : ((t == 1) ? (gr + gi) : (gi - gr));
    }
}

// IN_PLANAR: src is [2, 2^24] planar re/im. Otherwise interleaved float2.
// OUT_PLANAR: dst is planar. Otherwise interleaved float2.
template <int IN_PLANAR, int OUT_PLANAR>
__global__ __launch_bounds__(256, 3)
void qgate_kernel(const float* __restrict__ src,
                  float* __restrict__ dst,
                  const int* __restrict__ targets_raw,
                  int step) {
    const int tid = threadIdx.x;

    // dtype detect: int64 targets (<24) have zero odd 32-bit words
    int stride = (targets_raw[1] == 0 && targets_raw[3] == 0) ? 2 : 1;
    int q0 = targets_raw[(step * 4 + 0) * stride];
    int q1 = targets_raw[(step * 4 + 1) * stride];
    int q2 = targets_raw[(step * 4 + 2) * stride];
    int q3 = targets_raw[(step * 4 + 3) * stride];
    unsigned m0 = 1u << q0, m1 = 1u << q1, m2 = 1u << q2, m3 = 1u << q3;

    // sorted copy for ascending zero-bit insertion
    int a = q0, b = q1, c = q2, d = q3, t;
    if (a > b) { t = a; a = b; b = t; }
    if (c > d) { t = c; c = d; d = t; }
    if (a > c) { t = a; a = c; c = t; }
    if (b > d) { t = b; b = d; d = t; }
    if (b > c) { t = b; b = c; c = t; }

    unsigned g20 = blockIdx.x * 256u + tid;
    unsigned base = g20;
    base = ((base >> a) << (a + 1)) | (base & ((1u << a) - 1u));
    base = ((base >> b) << (b + 1)) | (base & ((1u << b) - 1u));
    base = ((base >> c) << (c + 1)) | (base & ((1u << c) - 1u));
    base = ((base >> d) << (d + 1)) | (base & ((1u << d) - 1u));

    // ---- gather 16 amplitudes, pack along k into f32x2 pairs ----
    u64 sr2[8], si2[8], u2[8];
#pragma unroll
    for (int kk = 0; kk < 8; kk++) {
        unsigned o0 = base + ((kk & 1) ? m1 : 0u) +
                      ((kk & 2) ? m2 : 0u) + ((kk & 4) ? m3 : 0u);
        unsigned o1 = o0 + m0;
        float r0, i0, r1, i1;
        if (IN_PLANAR) {
            r0 = src[o0];
            i0 = src[NSTATE + o0];
            r1 = src[o1];
            i1 = src[NSTATE + o1];
        } else {
            const float2* s2 = reinterpret_cast<const float2*>(src);
            float2 v0 = s2[o0];
            float2 v1 = s2[o1];
            r0 = v0.x; i0 = v0.y;
            r1 = v1.x; i1 = v1.y;
        }
        sr2[kk] = pack2(r0, r1);
        si2[kk] = pack2(i0, i1);
        u2[kk]  = add2(sr2[kk], si2[kk]);   // sr + si
    }

    const float* gbase = cGK + step * 768;
    const u64 NEG1 = pack2(-1.0f, -1.0f);
#pragma unroll
    for (int j = 0; j < 16; j++) {
        // Table rows from __constant__ (uniform LDCU). Rows: A=gr, B=gr+gi,
        // C=gi-gr; .x/.y of each ulonglong2 ARE the packed f32x2 pairs.
        const ulonglong2* A2 = reinterpret_cast<const ulonglong2*>(gbase + j * 16);
        const ulonglong2* B2 = reinterpret_cast<const ulonglong2*>(gbase + 256 + j * 16);
        const ulonglong2* C2 = reinterpret_cast<const ulonglong2*>(gbase + 512 + j * 16);
        ulonglong2 av = A2[0], bv = B2[0], cv = C2[0];
        u64 a1 = mul2(av.x, u2[0]);    // gr*(sr+si)
        u64 a2 = mul2(bv.x, si2[0]);   // (gr+gi)*si
        u64 a3 = mul2(cv.x, sr2[0]);   // (gi-gr)*sr
        fma2_acc(a1, av.y, u2[1]);
        fma2_acc(a2, bv.y, si2[1]);
        fma2_acc(a3, cv.y, sr2[1]);
#pragma unroll
        for (int q = 1; q < 4; q++) {
            av = A2[q]; bv = B2[q]; cv = C2[q];
            fma2_acc(a1, av.x, u2[2 * q]);
            fma2_acc(a2, bv.x, si2[2 * q]);
            fma2_acc(a3, cv.x, sr2[2 * q]);
            fma2_acc(a1, av.y, u2[2 * q + 1]);
            fma2_acc(a2, bv.y, si2[2 * q + 1]);
            fma2_acc(a3, cv.y, sr2[2 * q + 1]);
        }
        u64 dim = add2(a1, a3);        // im pair = a1 + a3 (before a1 is consumed)
        fma2_acc(a1, a2, NEG1);        // re pair = a1 - a2
        float rl, rh, il, ih;
        unpack2(a1, rl, rh);
        unpack2(dim, il, ih);
        float re = rl + rh;
        float im = il + ih;
        unsigned oj = base + ((j & 1) ? m0 : 0u) + ((j & 2) ? m1 : 0u) +
                      ((j & 4) ? m2 : 0u) + ((j & 8) ? m3 : 0u);
        if (OUT_PLANAR) {
            dst[oj] = re;
            dst[NSTATE + oj] = im;
        } else {
            reinterpret_cast<float2*>(dst)[oj] = make_float2(re, im);
        }
    }
}

extern "C" void kernel_launch(void* const* d_in, const int* in_sizes, int n_in,
                              void* d_out, int out_size) {
    const float* state   = (const float*)d_in[0];
    const int*   targets = (const int*)d_in[1];
    const float* gates   = (const float*)d_in[2];
    float*       out     = (float*)d_out;

    void* scratch_ptr = nullptr;
    cudaGetSymbolAddress(&scratch_ptr, QS_scratch);
    float* scratch = (float*)scratch_ptr;

    void* tables_ptr = nullptr;
    cudaGetSymbolAddress(&tables_ptr, QS_tables);

    // build Karatsuba tables, then upload to constant memory (DtoD, capture-safe)
    qprep_kernel<<<NSTEPS, 256>>>(gates);
    cudaMemcpyToSymbolAsync(cGK, tables_ptr, NSTEPS * 768 * sizeof(float), 0,
                            cudaMemcpyDeviceToDevice);

    dim3 block(256);
    dim3 grid(NGROUPS / 256);  // 4096 blocks

    // step 0: planar input -> interleaved scratch
    qgate_kernel<1, 0><<<grid, block>>>(state, scratch, targets, 0);
    // steps 1..6: interleaved in-place (each thread owns its group)
    for (int s = 1; s < NSTEPS - 1; s++) {
        qgate_kernel<0, 0><<<grid, block>>>(scratch, scratch, targets, s);
    }
    // step 7: interleaved -> planar output
    qgate_kernel<0, 1><<<grid, block>>>(scratch, out, targets, NSTEPS - 1);
}